// round 8
// baseline (speedup 1.0000x reference)
#include <cuda_runtime.h>
#include <math.h>

#define BB 4
#define CC 8
#define HH 256
#define WW 256
#define INF_D 512
#define JT 8                          // columns per colpass tile
#define NR 8                          // rows per colpass thread (interleaved)

// Static device scratch (no allocations allowed)
__device__ unsigned short g_gin[BB*CC*HH*WW];   // 4 MB: per-class row distance (inside)
__device__ unsigned short g_tr[BB*HH*WW];       // 0.5 MB: packed (t<<10 | r)
__device__ float          g_prob[BB*CC*HH*WW];  // 8 MB: softmax probabilities
__device__ int            g_cnt[BB*CC];         // class presence counts
__device__ float          g_part[BB*CC*(WW/JT)];// 1024 block partial sums

// ---------------------------------------------------------------------------
__global__ void k_init() {
    int i = threadIdx.x;
    if (i < BB*CC) g_cnt[i] = 0;
}

// Standalone softmax: one float2 (2 pixels) per thread, 131072 threads.
__global__ void k_softmax(const float* __restrict__ output) {
    const int q   = blockIdx.x * 128 + threadIdx.x;   // 0 .. 131071 (pixel/2)
    const int b   = q >> 15;
    const int hw2 = q & 32767;
    const float2* out2 = (const float2*)output;
    float2* prob2 = (float2*)g_prob;

    float2 lg[CC];
    float mx = -1e30f, my = -1e30f;
    #pragma unroll
    for (int c = 0; c < CC; ++c) {
        lg[c] = out2[(b*CC + c)*32768 + hw2];
        mx = fmaxf(mx, lg[c].x); my = fmaxf(my, lg[c].y);
    }
    float sx = 0.f, sy = 0.f;
    #pragma unroll
    for (int c = 0; c < CC; ++c) {
        lg[c].x = __expf(lg[c].x - mx); sx += lg[c].x;
        lg[c].y = __expf(lg[c].y - my); sy += lg[c].y;
    }
    const float ix = 1.f/sx, iy = 1.f/sy;
    #pragma unroll
    for (int c = 0; c < CC; ++c)
        prob2[(b*CC + c)*32768 + hw2] = make_float2(lg[c].x*ix, lg[c].y*iy);
}

// Nearest set bit distance in a 256-bit mask (8 words), bits optionally
// inverted by xor with `inv`. Returns 0 if bit j itself is set; INF_D if none.
__device__ __forceinline__ int nearest_bit(const unsigned* wd, unsigned inv, int j) {
    const int wj = j >> 5, bj = j & 31;
    const unsigned cur = wd[wj] ^ inv;
    int dl = INF_D, dr = INF_D;

    unsigned m = cur & (0xffffffffu >> (31 - bj));   // bits [0..bj]
    if (m) {
        dl = bj - (31 - __clz(m));
    } else {
        #pragma unroll
        for (int w = 6; w >= 0; --w) {               // first nonzero word below
            if (w < wj) {
                const unsigned mw = wd[w] ^ inv;
                if (mw) { dl = j - (w*32 + 31 - __clz(mw)); break; }
            }
        }
    }
    m = cur >> bj;                                   // bits [bj..31]
    if (m) {
        dr = __ffs(m) - 1;
    } else {
        #pragma unroll
        for (int w = 1; w <= 7; ++w) {               // first nonzero word above
            if (w > wj) {
                const unsigned mw = wd[w] ^ inv;
                if (mw) { dr = (w*32 + __ffs(mw) - 1) - j; break; }
            }
        }
    }
    int d = dl < dr ? dl : dr;
    return d < INF_D ? d : INF_D;
}

// Row pass: one block per (b, h) row. Bitmask-based nearest-site distances.
__global__ void k_rowpass(const int* __restrict__ target) {
    const int row = blockIdx.x;          // b*HH + h
    const int b   = row / HH;
    const int h   = row % HH;
    const int j   = threadIdx.x;
    const int w   = j >> 5;              // warp id 0..7
    const int ln  = j & 31;

    __shared__ unsigned mask[CC][8];     // 256-bit occupancy per class
    const int t = target[row * WW + j];

    #pragma unroll
    for (int c = 0; c < CC; ++c) {
        const unsigned m = __ballot_sync(0xffffffffu, t == c);
        if (ln == 0) mask[c][w] = m;
    }
    __syncthreads();

    // r: nearest column whose class differs from t  (complement of mask[t])
    const int r = nearest_bit(mask[t], 0xffffffffu, j);
    g_tr[row * WW + j] = (unsigned short)(r | (t << 10));

    // gin[c]: nearest column with class c
    #pragma unroll
    for (int c = 0; c < CC; ++c) {
        const int g = nearest_bit(mask[c], 0u, j);
        g_gin[((b*CC + c)*HH + h)*WW + j] = (unsigned short)g;
    }

    // presence counts: threads 0..7, one class each
    if (j < CC) {
        int cnt = 0;
        #pragma unroll
        for (int k = 0; k < 8; ++k) cnt += __popc(mask[j][k]);
        if (cnt) atomicAdd(&g_cnt[b*CC + j], cnt);
    }
}

// Fused column pass + weighted reduce: one block per (bc, 8-col tile).
// Each thread owns one column and 8 interleaved row-scans (register arrays)
// so the 4 LDS per row per d-iteration issue back-to-back (MLP ~32),
// hiding shared-memory latency. Exit when d^2 >= max over all 8 running
// minima — exact per the outward-scan argument applied per row.
__global__ void k_colpass() {
    const int jt  = blockIdx.x & (WW/JT - 1);   // 0..31
    const int bc  = blockIdx.x / (WW/JT);
    const int b   = bc >> 3;
    const int c   = bc & 7;
    const int j0  = jt * JT;

    __shared__ float s_in[HH][JT];
    __shared__ float s_out[HH][JT];

    const int jj = threadIdx.x & (JT - 1);
    const int k0 = threadIdx.x / JT;            // 0..31

    // Tile load: warp covers 4 rows x 8 cols per step.
    #pragma unroll
    for (int m = 0; m < NR; ++m) {
        const int k = k0 + 32*m;
        const unsigned v = g_tr[(b*HH + k)*WW + j0 + jj];
        const int t = (int)(v >> 10);
        const float gout = (t == c) ? (float)(v & 1023u) : 0.0f;
        const float gin  = (float)g_gin[(bc*HH + k)*WW + j0 + jj];
        s_in[k][jj]  = gin * gin;
        s_out[k][jj] = gout * gout;
    }
    __syncthreads();

    float din2[NR], dout2[NR];
    #pragma unroll
    for (int r = 0; r < NR; ++r) {
        const int i = k0 + 32*r;
        din2[r]  = s_in[i][jj];
        dout2[r] = s_out[i][jj];
    }

    for (int d = 1; d < HH; ++d) {
        const float dd2 = (float)(d * d);
        float mx = 0.0f;
        #pragma unroll
        for (int r = 0; r < NR; ++r)
            mx = fmaxf(mx, fmaxf(din2[r], dout2[r]));
        if (dd2 >= mx) break;

        #pragma unroll
        for (int r = 0; r < NR; ++r) {
            const int i  = k0 + 32*r;
            const int lo = i - d, hi = i + d;
            const float vli = (lo >= 0) ? s_in[lo][jj]  : 1e9f;
            const float vlo = (lo >= 0) ? s_out[lo][jj] : 1e9f;
            const float vhi = (hi < HH) ? s_in[hi][jj]  : 1e9f;
            const float vho = (hi < HH) ? s_out[hi][jj] : 1e9f;
            din2[r]  = fminf(din2[r],  fminf(dd2 + vli, dd2 + vhi));
            dout2[r] = fminf(dout2[r], fminf(dd2 + vlo, dd2 + vho));
        }
    }

    // prob-weighted accumulate
    float acc = 0.0f;
    #pragma unroll
    for (int r = 0; r < NR; ++r) {
        const int i = k0 + 32*r;
        const float dmap = sqrtf(din2[r]) - sqrtf(dout2[r]);
        acc += dmap * g_prob[(bc*HH + i)*WW + j0 + jj];
    }

    // Block reduce 256 partials -> 1, gate by presence.
    __syncthreads();                     // reuse s_in as reduce scratch
    float* sred = &s_in[0][0];
    sred[threadIdx.x] = acc;
    __syncthreads();
    #pragma unroll
    for (int s = 128; s > 0; s >>= 1) {
        if (threadIdx.x < s) sred[threadIdx.x] += sred[threadIdx.x + s];
        __syncthreads();
    }
    if (threadIdx.x == 0) {
        const float pres = (g_cnt[bc] > 0) ? 1.0f : 0.0f;
        g_part[blockIdx.x] = sred[0] * pres;
    }
}

__global__ void k_final(float* __restrict__ out) {
    __shared__ float sred[1024];
    const int i = threadIdx.x;
    sred[i] = g_part[i];
    __syncthreads();
    #pragma unroll
    for (int s = 512; s > 0; s >>= 1) {
        if (i < s) sred[i] += sred[i + s];
        __syncthreads();
    }
    if (i == 0) {
        int n = 0;
        #pragma unroll
        for (int k = 0; k < BB*CC; ++k) n += (g_cnt[k] > 0) ? 1 : 0;
        const float nf = (n > 0) ? (float)n : 1.0f;
        out[0] = sred[0] / nf;
    }
}

// ---------------------------------------------------------------------------
extern "C" void kernel_launch(void* const* d_in, const int* in_sizes, int n_in,
                              void* d_out, int out_size) {
    const float* output = (const float*)d_in[0];   // [4,8,256,256] fp32
    const int*   target = (const int*)d_in[1];     // [4,256,256] int32
    float*       out    = (float*)d_out;           // scalar

    k_init   <<<1, 32>>>();
    k_softmax<<<(BB*HH*WW)/(2*128), 128>>>(output);
    k_rowpass<<<BB*HH, WW>>>(target);
    k_colpass<<<BB*CC*(WW/JT), 256>>>();
    k_final  <<<1, 1024>>>(out);
}

// round 10
// speedup vs baseline: 1.0752x; 1.0752x over previous
#include <cuda_runtime.h>
#include <math.h>

#define BB 4
#define CC 8
#define HH 256
#define WW 256
#define INF_D 512
#define JT 8                          // columns per colpass tile
#define NR 8                          // rows per colpass thread (interleaved)
#define NIN  (BB*CC*(WW/JT))          // 1024 in-pass blocks
#define NOUT (BB*(WW/JT))             // 128 out-pass blocks

// Static device scratch (no allocations allowed)
__device__ unsigned short g_gin[BB*CC*HH*WW];   // 4 MB: per-class row distance (inside)
__device__ unsigned short g_tr[BB*HH*WW];       // 0.5 MB: packed (t<<10 | r)
__device__ float          g_prob[BB*CC*HH*WW];  // 8 MB: softmax probabilities
__device__ int            g_cnt[BB*CC];         // class presence counts
__device__ float          g_part[NIN + NOUT];   // block partial sums

// ---------------------------------------------------------------------------
__global__ void k_init() {
    int i = threadIdx.x;
    if (i < BB*CC) g_cnt[i] = 0;
}

// Standalone softmax: one float2 (2 pixels) per thread.
__global__ void k_softmax(const float* __restrict__ output) {
    const int q   = blockIdx.x * 128 + threadIdx.x;   // 0 .. 131071 (pixel/2)
    const int b   = q >> 15;
    const int hw2 = q & 32767;
    const float2* out2 = (const float2*)output;
    float2* prob2 = (float2*)g_prob;

    float2 lg[CC];
    float mx = -1e30f, my = -1e30f;
    #pragma unroll
    for (int c = 0; c < CC; ++c) {
        lg[c] = out2[(b*CC + c)*32768 + hw2];
        mx = fmaxf(mx, lg[c].x); my = fmaxf(my, lg[c].y);
    }
    float sx = 0.f, sy = 0.f;
    #pragma unroll
    for (int c = 0; c < CC; ++c) {
        lg[c].x = __expf(lg[c].x - mx); sx += lg[c].x;
        lg[c].y = __expf(lg[c].y - my); sy += lg[c].y;
    }
    const float ix = 1.f/sx, iy = 1.f/sy;
    #pragma unroll
    for (int c = 0; c < CC; ++c)
        prob2[(b*CC + c)*32768 + hw2] = make_float2(lg[c].x*ix, lg[c].y*iy);
}

// Nearest set bit distance in a 256-bit mask (8 words), bits optionally
// inverted by xor with `inv`. Returns 0 if bit j itself is set; INF_D if none.
__device__ __forceinline__ int nearest_bit(const unsigned* wd, unsigned inv, int j) {
    const int wj = j >> 5, bj = j & 31;
    const unsigned cur = wd[wj] ^ inv;
    int dl = INF_D, dr = INF_D;

    unsigned m = cur & (0xffffffffu >> (31 - bj));   // bits [0..bj]
    if (m) {
        dl = bj - (31 - __clz(m));
    } else {
        #pragma unroll
        for (int w = 6; w >= 0; --w) {
            if (w < wj) {
                const unsigned mw = wd[w] ^ inv;
                if (mw) { dl = j - (w*32 + 31 - __clz(mw)); break; }
            }
        }
    }
    m = cur >> bj;                                   // bits [bj..31]
    if (m) {
        dr = __ffs(m) - 1;
    } else {
        #pragma unroll
        for (int w = 1; w <= 7; ++w) {
            if (w > wj) {
                const unsigned mw = wd[w] ^ inv;
                if (mw) { dr = (w*32 + __ffs(mw) - 1) - j; break; }
            }
        }
    }
    int d = dl < dr ? dl : dr;
    return d < INF_D ? d : INF_D;
}

// Row pass: one block per (b, h) row. Bitmask-based nearest-site distances.
__global__ void k_rowpass(const int* __restrict__ target) {
    const int row = blockIdx.x;          // b*HH + h
    const int b   = row / HH;
    const int h   = row % HH;
    const int j   = threadIdx.x;
    const int w   = j >> 5;
    const int ln  = j & 31;

    __shared__ unsigned mask[CC][8];
    const int t = target[row * WW + j];

    #pragma unroll
    for (int c = 0; c < CC; ++c) {
        const unsigned m = __ballot_sync(0xffffffffu, t == c);
        if (ln == 0) mask[c][w] = m;
    }
    __syncthreads();

    const int r = nearest_bit(mask[t], 0xffffffffu, j);
    g_tr[row * WW + j] = (unsigned short)(r | (t << 10));

    #pragma unroll
    for (int c = 0; c < CC; ++c) {
        const int g = nearest_bit(mask[c], 0u, j);
        g_gin[((b*CC + c)*HH + h)*WW + j] = (unsigned short)g;
    }

    if (j < CC) {
        int cnt = 0;
        #pragma unroll
        for (int k = 0; k < 8; ++k) cnt += __popc(mask[j][k]);
        if (cnt) atomicAdd(&g_cnt[b*CC + j], cnt);
    }
}

// Inside column pass: one block per (bc, 8-col tile). Interleaved NR=8
// register scans; exact early exit (d^2 >= max running min). Accumulates
// prob_c * sqrt(din2), gated by class presence.
__global__ void k_colin() {
    const int jt  = blockIdx.x & (WW/JT - 1);
    const int bc  = blockIdx.x / (WW/JT);
    const int b   = bc >> 3;
    const int j0  = jt * JT;

    if (g_cnt[bc] == 0) {                       // absent class: zero partial
        if (threadIdx.x == 0) g_part[blockIdx.x] = 0.0f;
        return;
    }

    __shared__ float s_g2[HH][JT];

    const int jj = threadIdx.x & (JT - 1);
    const int k0 = threadIdx.x / JT;            // 0..31

    #pragma unroll
    for (int m = 0; m < NR; ++m) {
        const int k = k0 + 32*m;
        const float g = (float)g_gin[(bc*HH + k)*WW + j0 + jj];
        s_g2[k][jj] = g * g;
    }
    __syncthreads();

    float din2[NR];
    #pragma unroll
    for (int r = 0; r < NR; ++r) din2[r] = s_g2[k0 + 32*r][jj];

    for (int d = 1; d < HH; ++d) {
        const float dd2 = (float)(d * d);
        float mx = 0.0f;
        #pragma unroll
        for (int r = 0; r < NR; ++r) mx = fmaxf(mx, din2[r]);
        if (dd2 >= mx) break;

        #pragma unroll
        for (int r = 0; r < NR; ++r) {
            const int i  = k0 + 32*r;
            const int lo = i - d, hi = i + d;
            const float vlo = (lo >= 0) ? s_g2[lo][jj] : 1e9f;
            const float vhi = (hi < HH) ? s_g2[hi][jj] : 1e9f;
            din2[r] = fminf(din2[r], dd2 + fminf(vlo, vhi));
        }
    }

    float acc = 0.0f;
    #pragma unroll
    for (int r = 0; r < NR; ++r) {
        const int i = k0 + 32*r;
        acc += sqrtf(din2[r]) * g_prob[(bc*HH + i)*WW + j0 + jj];
    }

    __syncthreads();
    float* sred = &s_g2[0][0];
    sred[threadIdx.x] = acc;
    __syncthreads();
    #pragma unroll
    for (int s = 128; s > 0; s >>= 1) {
        if (threadIdx.x < s) sred[threadIdx.x] += sred[threadIdx.x + s];
        __syncthreads();
    }
    if (threadIdx.x == 0) g_part[blockIdx.x] = sred[0];
}

// Outside column pass, class-collapsed: sum_c prob_c*dout_c =
// prob_{t(x)}(x) * D_out(x), D_out = dist to nearest different-class pixel.
// Separable: D_out(i)^2 = min_k (i-k)^2 + (t(k)==t(i) ? r(k)^2 : 0).
// One block per (b, 8-col tile); accumulates NEGATIVE partials.
__global__ void k_colout() {
    const int jt  = blockIdx.x & (WW/JT - 1);
    const int b   = blockIdx.x / (WW/JT);
    const int j0  = jt * JT;

    __shared__ float s_r2[HH][JT];
    __shared__ int   s_t[HH][JT];

    const int jj = threadIdx.x & (JT - 1);
    const int k0 = threadIdx.x / JT;            // 0..31

    #pragma unroll
    for (int m = 0; m < NR; ++m) {
        const int k = k0 + 32*m;
        const unsigned v = g_tr[(b*HH + k)*WW + j0 + jj];
        const float rr = (float)(v & 1023u);
        s_r2[k][jj] = rr * rr;
        s_t[k][jj]  = (int)(v >> 10);
    }
    __syncthreads();

    float dout2[NR];
    int   tc[NR];
    #pragma unroll
    for (int r = 0; r < NR; ++r) {
        const int i = k0 + 32*r;
        tc[r]    = s_t[i][jj];
        dout2[r] = s_r2[i][jj];
    }

    for (int d = 1; d < HH; ++d) {
        const float dd2 = (float)(d * d);
        float mx = 0.0f;
        #pragma unroll
        for (int r = 0; r < NR; ++r) mx = fmaxf(mx, dout2[r]);
        if (dd2 >= mx) break;

        #pragma unroll
        for (int r = 0; r < NR; ++r) {
            const int i  = k0 + 32*r;
            const int lo = i - d, hi = i + d;
            float vlo = 1e9f, vhi = 1e9f;
            if (lo >= 0) vlo = (s_t[lo][jj] == tc[r]) ? s_r2[lo][jj] : 0.0f;
            if (hi < HH) vhi = (s_t[hi][jj] == tc[r]) ? s_r2[hi][jj] : 0.0f;
            dout2[r] = fminf(dout2[r], dd2 + fminf(vlo, vhi));
        }
    }

    float acc = 0.0f;
    #pragma unroll
    for (int r = 0; r < NR; ++r) {
        const int i = k0 + 32*r;
        const float p = g_prob[((b*CC + tc[r])*HH + i)*WW + j0 + jj];
        acc -= sqrtf(dout2[r]) * p;
    }

    __syncthreads();
    float* sred = &s_r2[0][0];
    sred[threadIdx.x] = acc;
    __syncthreads();
    #pragma unroll
    for (int s = 128; s > 0; s >>= 1) {
        if (threadIdx.x < s) sred[threadIdx.x] += sred[threadIdx.x + s];
        __syncthreads();
    }
    if (threadIdx.x == 0) g_part[NIN + blockIdx.x] = sred[0];
}

__global__ void k_final(float* __restrict__ out) {
    __shared__ float sred[1024];
    const int i = threadIdx.x;
    float v = g_part[i];
    if (i < NOUT) v += g_part[NIN + i];
    sred[i] = v;
    __syncthreads();
    #pragma unroll
    for (int s = 512; s > 0; s >>= 1) {
        if (i < s) sred[i] += sred[i + s];
        __syncthreads();
    }
    if (i == 0) {
        int n = 0;
        #pragma unroll
        for (int k = 0; k < BB*CC; ++k) n += (g_cnt[k] > 0) ? 1 : 0;
        const float nf = (n > 0) ? (float)n : 1.0f;
        out[0] = sred[0] / nf;
    }
}

// ---------------------------------------------------------------------------
extern "C" void kernel_launch(void* const* d_in, const int* in_sizes, int n_in,
                              void* d_out, int out_size) {
    const float* output = (const float*)d_in[0];   // [4,8,256,256] fp32
    const int*   target = (const int*)d_in[1];     // [4,256,256] int32
    float*       out    = (float*)d_out;           // scalar

    k_init   <<<1, 32>>>();
    k_softmax<<<(BB*HH*WW)/(2*128), 128>>>(output);
    k_rowpass<<<BB*HH, WW>>>(target);
    k_colin  <<<NIN,  256>>>();
    k_colout <<<NOUT, 256>>>();
    k_final  <<<1, 1024>>>(out);
}

// round 11
// speedup vs baseline: 1.0864x; 1.0104x over previous
#include <cuda_runtime.h>
#include <math.h>

#define BB 4
#define CC 8
#define HH 256
#define WW 256
#define INF_D 512
#define JT 8                          // columns per colpass tile
#define NR 8                          // rows per colpass thread (interleaved)
#define NIN  (BB*CC*(WW/JT))          // 1024 in-pass blocks
#define NOUT (BB*(WW/JT))             // 128 out-pass blocks

// Static device scratch (no allocations allowed)
__device__ unsigned short g_gin[BB*CC*HH*WW];   // 4 MB: per-class row distance (inside)
__device__ unsigned short g_tr[BB*HH*WW];       // 0.5 MB: packed (t<<10 | r)
__device__ float          g_prob[BB*CC*HH*WW];  // 8 MB: softmax probabilities
__device__ int            g_cnt[BB*CC];         // class presence counts
__device__ float          g_part[NIN + NOUT];   // block partial sums

// ---------------------------------------------------------------------------
// Softmax: one float2 (2 pixels) per thread. Block 0 also zeroes g_cnt
// (safe: rowpass's atomics run in a later kernel, stream-ordered).
__global__ void k_softmax(const float* __restrict__ output) {
    if (blockIdx.x == 0 && threadIdx.x < BB*CC) g_cnt[threadIdx.x] = 0;

    const int q   = blockIdx.x * 128 + threadIdx.x;   // 0 .. 131071 (pixel/2)
    const int b   = q >> 15;
    const int hw2 = q & 32767;
    const float2* out2 = (const float2*)output;
    float2* prob2 = (float2*)g_prob;

    float2 lg[CC];
    float mx = -1e30f, my = -1e30f;
    #pragma unroll
    for (int c = 0; c < CC; ++c) {
        lg[c] = out2[(b*CC + c)*32768 + hw2];
        mx = fmaxf(mx, lg[c].x); my = fmaxf(my, lg[c].y);
    }
    float sx = 0.f, sy = 0.f;
    #pragma unroll
    for (int c = 0; c < CC; ++c) {
        lg[c].x = __expf(lg[c].x - mx); sx += lg[c].x;
        lg[c].y = __expf(lg[c].y - my); sy += lg[c].y;
    }
    const float ix = 1.f/sx, iy = 1.f/sy;
    #pragma unroll
    for (int c = 0; c < CC; ++c)
        prob2[(b*CC + c)*32768 + hw2] = make_float2(lg[c].x*ix, lg[c].y*iy);
}

// Nearest set bit distance in a 256-bit mask (8 words), bits optionally
// inverted by xor with `inv`. Returns 0 if bit j itself is set; INF_D if none.
__device__ __forceinline__ int nearest_bit(const unsigned* wd, unsigned inv, int j) {
    const int wj = j >> 5, bj = j & 31;
    const unsigned cur = wd[wj] ^ inv;
    int dl = INF_D, dr = INF_D;

    unsigned m = cur & (0xffffffffu >> (31 - bj));   // bits [0..bj]
    if (m) {
        dl = bj - (31 - __clz(m));
    } else {
        #pragma unroll
        for (int w = 6; w >= 0; --w) {
            if (w < wj) {
                const unsigned mw = wd[w] ^ inv;
                if (mw) { dl = j - (w*32 + 31 - __clz(mw)); break; }
            }
        }
    }
    m = cur >> bj;                                   // bits [bj..31]
    if (m) {
        dr = __ffs(m) - 1;
    } else {
        #pragma unroll
        for (int w = 1; w <= 7; ++w) {
            if (w > wj) {
                const unsigned mw = wd[w] ^ inv;
                if (mw) { dr = (w*32 + __ffs(mw) - 1) - j; break; }
            }
        }
    }
    int d = dl < dr ? dl : dr;
    return d < INF_D ? d : INF_D;
}

// Row pass: one block per (b, h) row. Bitmask-based nearest-site distances.
__global__ void k_rowpass(const int* __restrict__ target) {
    const int row = blockIdx.x;          // b*HH + h
    const int b   = row / HH;
    const int h   = row % HH;
    const int j   = threadIdx.x;
    const int w   = j >> 5;
    const int ln  = j & 31;

    __shared__ unsigned mask[CC][8];
    const int t = target[row * WW + j];

    #pragma unroll
    for (int c = 0; c < CC; ++c) {
        const unsigned m = __ballot_sync(0xffffffffu, t == c);
        if (ln == 0) mask[c][w] = m;
    }
    __syncthreads();

    const int r = nearest_bit(mask[t], 0xffffffffu, j);
    g_tr[row * WW + j] = (unsigned short)(r | (t << 10));

    #pragma unroll
    for (int c = 0; c < CC; ++c) {
        const int g = nearest_bit(mask[c], 0u, j);
        g_gin[((b*CC + c)*HH + h)*WW + j] = (unsigned short)g;
    }

    if (j < CC) {
        int cnt = 0;
        #pragma unroll
        for (int k = 0; k < 8; ++k) cnt += __popc(mask[j][k]);
        if (cnt) atomicAdd(&g_cnt[b*CC + j], cnt);
    }
}

// Deterministic block reduce: warp butterfly + cross-warp sum.
__device__ __forceinline__ void block_reduce_write(float acc, float* dst) {
    #pragma unroll
    for (int o = 16; o > 0; o >>= 1)
        acc += __shfl_xor_sync(0xffffffffu, acc, o);
    __shared__ float swarp[8];
    if ((threadIdx.x & 31) == 0) swarp[threadIdx.x >> 5] = acc;
    __syncthreads();
    if (threadIdx.x == 0) {
        float s0 = 0.f;
        #pragma unroll
        for (int w = 0; w < 8; ++w) s0 += swarp[w];
        *dst = s0;
    }
}

// Inside column pass: one block per (bc, 8-col tile). Interleaved NR=8
// register scans, SOFTWARE-PIPELINED: loads for step d+1 are issued before
// the exit check for step d resolves (addresses depend only on d), so LDS
// latency overlaps the min-update and max-tree. Exact early exit.
__global__ void k_colin() {
    const int jt  = blockIdx.x & (WW/JT - 1);
    const int bc  = blockIdx.x / (WW/JT);
    const int j0  = jt * JT;

    if (g_cnt[bc] == 0) {
        if (threadIdx.x == 0) g_part[blockIdx.x] = 0.0f;
        return;
    }

    __shared__ float s[HH*JT];
    const int jj = threadIdx.x & (JT - 1);
    const int k0 = threadIdx.x / JT;            // 0..31

    #pragma unroll
    for (int m = 0; m < NR; ++m) {
        const int k = k0 + 32*m;
        const float g = (float)g_gin[(bc*HH + k)*WW + j0 + jj];
        s[k*JT + jj] = g * g;
    }
    __syncthreads();

    float din2[NR], vlo[NR], vhi[NR];
    #pragma unroll
    for (int r = 0; r < NR; ++r) {
        const int i = k0 + 32*r;
        din2[r] = s[i*JT + jj];
        vlo[r]  = (i-1 >= 0) ? s[(i-1)*JT + jj] : 1e9f;
        vhi[r]  = (i+1 < HH) ? s[(i+1)*JT + jj] : 1e9f;
    }
    float mx = 0.f;
    #pragma unroll
    for (int r = 0; r < NR; ++r) mx = fmaxf(mx, din2[r]);

    for (int d = 1; d < HH; ++d) {
        const float dd2 = (float)(d * d);
        if (dd2 >= mx) break;
        #pragma unroll
        for (int r = 0; r < NR; ++r)
            din2[r] = fminf(din2[r], dd2 + fminf(vlo[r], vhi[r]));
        #pragma unroll
        for (int r = 0; r < NR; ++r) {          // prefetch step d+1
            const int i  = k0 + 32*r;
            const int lo = i - d - 1, hi = i + d + 1;
            vlo[r] = (lo >= 0) ? s[lo*JT + jj] : 1e9f;
            vhi[r] = (hi < HH) ? s[hi*JT + jj] : 1e9f;
        }
        mx = 0.f;
        #pragma unroll
        for (int r = 0; r < NR; ++r) mx = fmaxf(mx, din2[r]);
    }

    float acc = 0.0f;
    #pragma unroll
    for (int r = 0; r < NR; ++r) {
        const int i = k0 + 32*r;
        acc += sqrtf(din2[r]) * g_prob[(bc*HH + i)*WW + j0 + jj];
    }
    block_reduce_write(acc, &g_part[blockIdx.x]);
}

// Outside column pass, class-collapsed (sum_c prob_c*dout_c =
// prob_{t(x)}(x)*D_out(x)). Packed smem word (r^2<<3 | t) halves LDS count;
// same software pipeline. Accumulates NEGATIVE partials.
__global__ void k_colout() {
    const int jt  = blockIdx.x & (WW/JT - 1);
    const int b   = blockIdx.x / (WW/JT);
    const int j0  = jt * JT;

    __shared__ int s[HH*JT];
    const int jj = threadIdx.x & (JT - 1);
    const int k0 = threadIdx.x / JT;

    #pragma unroll
    for (int m = 0; m < NR; ++m) {
        const int k = k0 + 32*m;
        const unsigned v = g_tr[(b*HH + k)*WW + j0 + jj];
        const int rr = (int)(v & 1023u);
        s[k*JT + jj] = (rr*rr*8) | (int)(v >> 10);   // r^2<<3 | t
    }
    __syncthreads();

    float dout2[NR];
    int   tc[NR], plo[NR], phi[NR];
    #pragma unroll
    for (int r = 0; r < NR; ++r) {
        const int i  = k0 + 32*r;
        const int pv = s[i*JT + jj];
        tc[r]    = pv & 7;
        dout2[r] = (float)(pv >> 3);
        plo[r]   = (i-1 >= 0) ? s[(i-1)*JT + jj] : -1;
        phi[r]   = (i+1 < HH) ? s[(i+1)*JT + jj] : -1;
    }
    float mx = 0.f;
    #pragma unroll
    for (int r = 0; r < NR; ++r) mx = fmaxf(mx, dout2[r]);

    for (int d = 1; d < HH; ++d) {
        const float dd2 = (float)(d * d);
        if (dd2 >= mx) break;
        #pragma unroll
        for (int r = 0; r < NR; ++r) {
            const float vl = (plo[r] < 0) ? 1e9f
                           : (((plo[r] & 7) == tc[r]) ? (float)(plo[r] >> 3) : 0.0f);
            const float vh = (phi[r] < 0) ? 1e9f
                           : (((phi[r] & 7) == tc[r]) ? (float)(phi[r] >> 3) : 0.0f);
            dout2[r] = fminf(dout2[r], dd2 + fminf(vl, vh));
        }
        #pragma unroll
        for (int r = 0; r < NR; ++r) {          // prefetch step d+1
            const int i  = k0 + 32*r;
            const int lo = i - d - 1, hi = i + d + 1;
            plo[r] = (lo >= 0) ? s[lo*JT + jj] : -1;
            phi[r] = (hi < HH) ? s[hi*JT + jj] : -1;
        }
        mx = 0.f;
        #pragma unroll
        for (int r = 0; r < NR; ++r) mx = fmaxf(mx, dout2[r]);
    }

    float acc = 0.0f;
    #pragma unroll
    for (int r = 0; r < NR; ++r) {
        const int i = k0 + 32*r;
        const float p = g_prob[((b*CC + tc[r])*HH + i)*WW + j0 + jj];
        acc -= sqrtf(dout2[r]) * p;
    }
    block_reduce_write(acc, &g_part[NIN + blockIdx.x]);
}

__global__ void k_final(float* __restrict__ out) {
    __shared__ float sred[1024];
    const int i = threadIdx.x;
    float v = g_part[i];
    if (i < NOUT) v += g_part[NIN + i];
    sred[i] = v;
    __syncthreads();
    #pragma unroll
    for (int s = 512; s > 0; s >>= 1) {
        if (i < s) sred[i] += sred[i + s];
        __syncthreads();
    }
    if (i == 0) {
        int n = 0;
        #pragma unroll
        for (int k = 0; k < BB*CC; ++k) n += (g_cnt[k] > 0) ? 1 : 0;
        const float nf = (n > 0) ? (float)n : 1.0f;
        out[0] = sred[0] / nf;
    }
}

// ---------------------------------------------------------------------------
extern "C" void kernel_launch(void* const* d_in, const int* in_sizes, int n_in,
                              void* d_out, int out_size) {
    const float* output = (const float*)d_in[0];   // [4,8,256,256] fp32
    const int*   target = (const int*)d_in[1];     // [4,256,256] int32
    float*       out    = (float*)d_out;           // scalar

    k_softmax<<<(BB*HH*WW)/(2*128), 128>>>(output);
    k_rowpass<<<BB*HH, WW>>>(target);
    k_colin  <<<NIN,  256>>>();
    k_colout <<<NOUT, 256>>>();
    k_final  <<<1, 1024>>>(out);
}

// round 12
// speedup vs baseline: 1.1652x; 1.0725x over previous
#include <cuda_runtime.h>
#include <math.h>

#define BB 4
#define CC 8
#define HH 256
#define WW 256
#define INF_D 512
#define JT 8                          // columns per colin tile
#define NR 8                          // rows per colin thread (interleaved)
#define JTO 2                         // columns per colout tile
#define NRO 2                         // rows per colout thread
#define NIN  (BB*CC*(WW/JT))          // 1024 colin blocks
#define NOUT (BB*(WW/JTO))            // 512 colout blocks

// Static device scratch (no allocations allowed)
__device__ unsigned short g_gin[BB*CC*HH*WW];   // 4 MB: per-class row distance (inside)
__device__ unsigned short g_tr[BB*HH*WW];       // 0.5 MB: packed (t<<10 | r)
__device__ float          g_prob[BB*CC*HH*WW];  // 8 MB: softmax probabilities
__device__ int            g_cnt[BB*CC];         // class presence counts
__device__ float          g_part[NIN + NOUT];   // block partial sums

// ---------------------------------------------------------------------------
// Softmax: one float2 (2 pixels) per thread. Block 0 also zeroes g_cnt
// (safe: rowpass's atomics run in a later kernel, stream-ordered).
__global__ void k_softmax(const float* __restrict__ output) {
    if (blockIdx.x == 0 && threadIdx.x < BB*CC) g_cnt[threadIdx.x] = 0;

    const int q   = blockIdx.x * 128 + threadIdx.x;   // 0 .. 131071 (pixel/2)
    const int b   = q >> 15;
    const int hw2 = q & 32767;
    const float2* out2 = (const float2*)output;
    float2* prob2 = (float2*)g_prob;

    float2 lg[CC];
    float mx = -1e30f, my = -1e30f;
    #pragma unroll
    for (int c = 0; c < CC; ++c) {
        lg[c] = out2[(b*CC + c)*32768 + hw2];
        mx = fmaxf(mx, lg[c].x); my = fmaxf(my, lg[c].y);
    }
    float sx = 0.f, sy = 0.f;
    #pragma unroll
    for (int c = 0; c < CC; ++c) {
        lg[c].x = __expf(lg[c].x - mx); sx += lg[c].x;
        lg[c].y = __expf(lg[c].y - my); sy += lg[c].y;
    }
    const float ix = 1.f/sx, iy = 1.f/sy;
    #pragma unroll
    for (int c = 0; c < CC; ++c)
        prob2[(b*CC + c)*32768 + hw2] = make_float2(lg[c].x*ix, lg[c].y*iy);
}

// Nearest set bit distance in a 256-bit mask (8 words), bits optionally
// inverted by xor with `inv`. Returns 0 if bit j itself is set; INF_D if none.
__device__ __forceinline__ int nearest_bit(const unsigned* wd, unsigned inv, int j) {
    const int wj = j >> 5, bj = j & 31;
    const unsigned cur = wd[wj] ^ inv;
    int dl = INF_D, dr = INF_D;

    unsigned m = cur & (0xffffffffu >> (31 - bj));   // bits [0..bj]
    if (m) {
        dl = bj - (31 - __clz(m));
    } else {
        #pragma unroll
        for (int w = 6; w >= 0; --w) {
            if (w < wj) {
                const unsigned mw = wd[w] ^ inv;
                if (mw) { dl = j - (w*32 + 31 - __clz(mw)); break; }
            }
        }
    }
    m = cur >> bj;                                   // bits [bj..31]
    if (m) {
        dr = __ffs(m) - 1;
    } else {
        #pragma unroll
        for (int w = 1; w <= 7; ++w) {
            if (w > wj) {
                const unsigned mw = wd[w] ^ inv;
                if (mw) { dr = (w*32 + __ffs(mw) - 1) - j; break; }
            }
        }
    }
    int d = dl < dr ? dl : dr;
    return d < INF_D ? d : INF_D;
}

// Row pass: one block per (b, h) row. Bitmask-based nearest-site distances.
__global__ void k_rowpass(const int* __restrict__ target) {
    const int row = blockIdx.x;          // b*HH + h
    const int b   = row / HH;
    const int h   = row % HH;
    const int j   = threadIdx.x;
    const int w   = j >> 5;
    const int ln  = j & 31;

    __shared__ unsigned mask[CC][8];
    const int t = target[row * WW + j];

    #pragma unroll
    for (int c = 0; c < CC; ++c) {
        const unsigned m = __ballot_sync(0xffffffffu, t == c);
        if (ln == 0) mask[c][w] = m;
    }
    __syncthreads();

    const int r = nearest_bit(mask[t], 0xffffffffu, j);
    g_tr[row * WW + j] = (unsigned short)(r | (t << 10));

    #pragma unroll
    for (int c = 0; c < CC; ++c) {
        const int g = nearest_bit(mask[c], 0u, j);
        g_gin[((b*CC + c)*HH + h)*WW + j] = (unsigned short)g;
    }

    if (j < CC) {
        int cnt = 0;
        #pragma unroll
        for (int k = 0; k < 8; ++k) cnt += __popc(mask[j][k]);
        if (cnt) atomicAdd(&g_cnt[b*CC + j], cnt);
    }
}

// Deterministic block reduce: warp butterfly + cross-warp sum.
__device__ __forceinline__ void block_reduce_write(float acc, float* dst) {
    #pragma unroll
    for (int o = 16; o > 0; o >>= 1)
        acc += __shfl_xor_sync(0xffffffffu, acc, o);
    __shared__ float swarp[8];
    if ((threadIdx.x & 31) == 0) swarp[threadIdx.x >> 5] = acc;
    __syncthreads();
    if (threadIdx.x == 0) {
        float s0 = 0.f;
        #pragma unroll
        for (int w = 0; w < 8; ++w) s0 += swarp[w];
        *dst = s0;
    }
}

// Merged column pass. Blocks [0, NIN): inside transform (per-class, JT=8,
// NR=8, software-pipelined early-exit scan). Blocks [NIN, NIN+NOUT):
// class-collapsed outside transform (JTO=2, NRO=2 -> 512 wide blocks that
// backfill SMs during the colin tail). Both write one partial each.
__global__ void k_col() {
    __shared__ float s[HH*JT];                  // 8 KB, aliased by both paths

    if (blockIdx.x < NIN) {
        // ---------------- inside transform ----------------
        const int jt  = blockIdx.x & (WW/JT - 1);
        const int bc  = blockIdx.x / (WW/JT);
        const int j0  = jt * JT;

        if (g_cnt[bc] == 0) {
            if (threadIdx.x == 0) g_part[blockIdx.x] = 0.0f;
            return;
        }

        const int jj = threadIdx.x & (JT - 1);
        const int k0 = threadIdx.x / JT;        // 0..31

        #pragma unroll
        for (int m = 0; m < NR; ++m) {
            const int k = k0 + 32*m;
            const float g = (float)g_gin[(bc*HH + k)*WW + j0 + jj];
            s[k*JT + jj] = g * g;
        }
        __syncthreads();

        float din2[NR], vlo[NR], vhi[NR];
        #pragma unroll
        for (int r = 0; r < NR; ++r) {
            const int i = k0 + 32*r;
            din2[r] = s[i*JT + jj];
            vlo[r]  = (i-1 >= 0) ? s[(i-1)*JT + jj] : 1e9f;
            vhi[r]  = (i+1 < HH) ? s[(i+1)*JT + jj] : 1e9f;
        }
        float mx = 0.f;
        #pragma unroll
        for (int r = 0; r < NR; ++r) mx = fmaxf(mx, din2[r]);

        for (int d = 1; d < HH; ++d) {
            const float dd2 = (float)(d * d);
            if (dd2 >= mx) break;
            #pragma unroll
            for (int r = 0; r < NR; ++r)
                din2[r] = fminf(din2[r], dd2 + fminf(vlo[r], vhi[r]));
            #pragma unroll
            for (int r = 0; r < NR; ++r) {      // prefetch step d+1
                const int i  = k0 + 32*r;
                const int lo = i - d - 1, hi = i + d + 1;
                vlo[r] = (lo >= 0) ? s[lo*JT + jj] : 1e9f;
                vhi[r] = (hi < HH) ? s[hi*JT + jj] : 1e9f;
            }
            mx = 0.f;
            #pragma unroll
            for (int r = 0; r < NR; ++r) mx = fmaxf(mx, din2[r]);
        }

        float acc = 0.0f;
        #pragma unroll
        for (int r = 0; r < NR; ++r) {
            const int i = k0 + 32*r;
            acc += sqrtf(din2[r]) * g_prob[(bc*HH + i)*WW + j0 + jj];
        }
        block_reduce_write(acc, &g_part[blockIdx.x]);
    } else {
        // ------------- outside transform (collapsed) -------------
        const int bid = blockIdx.x - NIN;       // 0..511
        const int jt  = bid & (WW/JTO - 1);     // 0..127
        const int b   = bid / (WW/JTO);
        const int j0  = jt * JTO;

        int* si = (int*)s;
        const int jj = threadIdx.x & (JTO - 1); // 0..1
        const int k0 = threadIdx.x / JTO;       // 0..127

        #pragma unroll
        for (int m = 0; m < NRO; ++m) {
            const int k = k0 + 128*m;
            const unsigned v = g_tr[(b*HH + k)*WW + j0 + jj];
            const int rr = (int)(v & 1023u);
            si[k*JTO + jj] = (rr*rr*8) | (int)(v >> 10);   // r^2<<3 | t
        }
        __syncthreads();

        float dout2[NRO];
        int   tc[NRO], plo[NRO], phi[NRO];
        #pragma unroll
        for (int r = 0; r < NRO; ++r) {
            const int i  = k0 + 128*r;
            const int pv = si[i*JTO + jj];
            tc[r]    = pv & 7;
            dout2[r] = (float)(pv >> 3);
            plo[r]   = (i-1 >= 0) ? si[(i-1)*JTO + jj] : -1;
            phi[r]   = (i+1 < HH) ? si[(i+1)*JTO + jj] : -1;
        }
        float mx = 0.f;
        #pragma unroll
        for (int r = 0; r < NRO; ++r) mx = fmaxf(mx, dout2[r]);

        for (int d = 1; d < HH; ++d) {
            const float dd2 = (float)(d * d);
            if (dd2 >= mx) break;
            #pragma unroll
            for (int r = 0; r < NRO; ++r) {
                const float vl = (plo[r] < 0) ? 1e9f
                               : (((plo[r] & 7) == tc[r]) ? (float)(plo[r] >> 3) : 0.0f);
                const float vh = (phi[r] < 0) ? 1e9f
                               : (((phi[r] & 7) == tc[r]) ? (float)(phi[r] >> 3) : 0.0f);
                dout2[r] = fminf(dout2[r], dd2 + fminf(vl, vh));
            }
            #pragma unroll
            for (int r = 0; r < NRO; ++r) {     // prefetch step d+1
                const int i  = k0 + 128*r;
                const int lo = i - d - 1, hi = i + d + 1;
                plo[r] = (lo >= 0) ? si[lo*JTO + jj] : -1;
                phi[r] = (hi < HH) ? si[hi*JTO + jj] : -1;
            }
            mx = 0.f;
            #pragma unroll
            for (int r = 0; r < NRO; ++r) mx = fmaxf(mx, dout2[r]);
        }

        float acc = 0.0f;
        #pragma unroll
        for (int r = 0; r < NRO; ++r) {
            const int i = k0 + 128*r;
            const float p = g_prob[((b*CC + tc[r])*HH + i)*WW + j0 + jj];
            acc -= sqrtf(dout2[r]) * p;
        }
        block_reduce_write(acc, &g_part[blockIdx.x]);
    }
}

__global__ void k_final(float* __restrict__ out) {
    __shared__ float sred[1024];
    const int i = threadIdx.x;
    float v = g_part[i];
    if (i < NOUT) v += g_part[NIN + i];
    sred[i] = v;
    __syncthreads();
    #pragma unroll
    for (int s = 512; s > 0; s >>= 1) {
        if (i < s) sred[i] += sred[i + s];
        __syncthreads();
    }
    if (i == 0) {
        int n = 0;
        #pragma unroll
        for (int k = 0; k < BB*CC; ++k) n += (g_cnt[k] > 0) ? 1 : 0;
        const float nf = (n > 0) ? (float)n : 1.0f;
        out[0] = sred[0] / nf;
    }
}

// ---------------------------------------------------------------------------
extern "C" void kernel_launch(void* const* d_in, const int* in_sizes, int n_in,
                              void* d_out, int out_size) {
    const float* output = (const float*)d_in[0];   // [4,8,256,256] fp32
    const int*   target = (const int*)d_in[1];     // [4,256,256] int32
    float*       out    = (float*)d_out;           // scalar

    k_softmax<<<(BB*HH*WW)/(2*128), 128>>>(output);
    k_rowpass<<<BB*HH, WW>>>(target);
    k_col    <<<NIN + NOUT, 256>>>();
    k_final  <<<1, 1024>>>(out);
}